// round 2
// baseline (speedup 1.0000x reference)
#include <cuda_runtime.h>
#include <cuda_bf16.h>

// Problem constants (fixed by reference setup_inputs)
#define NB        4
#define CHN       256
#define FH        96
#define FW        96
#define PIX       (FH * FW)          // 9216
#define OUTS      7
#define SAMPLE    2
#define GRID14    (OUTS * SAMPLE)    // 14
#define NBINS     (OUTS * OUTS)      // 49
#define SCALE     0.0625f
#define CHN4      (CHN / 4)          // 64 float4 per pixel

// Scratch: features transposed to NHWC [n][y][x][c] for coalesced channel gathers.
__device__ float g_featT[(size_t)NB * PIX * CHN];   // 37.75 MB

// ---------------------------------------------------------------------------
// Pass 1: NCHW -> NHWC transpose. Per n: transpose (C=256, P=9216) -> (P, C).
// 32x32 smem tiles; P = 288*32 and C = 8*32 exactly, so no bounds checks.
// ---------------------------------------------------------------------------
__global__ void __launch_bounds__(256) transpose_kernel(const float* __restrict__ in) {
    __shared__ float tile[32][33];
    const int n  = blockIdx.z;
    const int p0 = blockIdx.x * 32;   // pixel tile
    const int c0 = blockIdx.y * 32;   // channel tile
    const int tx = threadIdx.x;       // 0..31
    const int ty = threadIdx.y;       // 0..7

    const float* src = in + (size_t)n * CHN * PIX;
#pragma unroll
    for (int i = 0; i < 32; i += 8) {
        // read coalesced along pixel dim
        tile[ty + i][tx] = src[(size_t)(c0 + ty + i) * PIX + (p0 + tx)];
    }
    __syncthreads();
    float* dst = g_featT + (size_t)n * PIX * CHN;
#pragma unroll
    for (int i = 0; i < 32; i += 8) {
        // write coalesced along channel dim
        dst[(size_t)(p0 + ty + i) * CHN + (c0 + tx)] = tile[tx][ty + i];
    }
}

// ---------------------------------------------------------------------------
// Pass 2: one CTA per roi. 256 threads = 64 channel-groups (float4 = 4 ch)
// x 4 concurrent bin-groups. Coord tables precomputed once per CTA in smem.
// Output staged in smem, then coalesced block copy.
// ---------------------------------------------------------------------------
__global__ void __launch_bounds__(256) roialign_kernel(const float* __restrict__ rois,
                                                       float* __restrict__ out) {
    extern __shared__ float s_out[];          // NBINS * CHN floats (49 KB)
    __shared__ int   s_ylo[GRID14], s_yhi[GRID14], s_xlo[GRID14], s_xhi[GRID14];
    __shared__ float s_fy[GRID14],  s_fx[GRID14];
    __shared__ int   s_vy[GRID14],  s_vx[GRID14];
    __shared__ float s_roi[5];

    const int k   = blockIdx.x;
    const int tid = threadIdx.x;
    const int cg  = tid & 63;         // channel group: channels cg*4 .. cg*4+3
    const int bg  = tid >> 6;         // bin group: bins bg, bg+4, bg+8, ...

    if (tid < 5) s_roi[tid] = rois[k * 5 + tid];
    __syncthreads();

    const int   n  = (int)s_roi[0];
    const float x1 = s_roi[1] * SCALE;
    const float y1 = s_roi[2] * SCALE;
    const float x2 = s_roi[3] * SCALE;
    const float y2 = s_roi[4] * SCALE;
    const float bin_w = fmaxf(x2 - x1, 1.0f) * (1.0f / OUTS);
    const float bin_h = fmaxf(y2 - y1, 1.0f) * (1.0f / OUTS);

    // Precompute 1D interpolation tables (14 y + 14 x) with 28 threads.
    if (tid < 2 * GRID14) {
        const int  g    = tid % GRID14;
        const bool isx  = tid >= GRID14;
        const float start = isx ? x1 : y1;
        const float bs    = isx ? bin_w : bin_h;
        const float size  = isx ? (float)FW : (float)FH;   // both 96

        const float off   = (float)(g / SAMPLE) + ((float)(g % SAMPLE) + 0.5f) / (float)SAMPLE;
        const float coord = start + bs * off;
        const int   valid = (coord >= -1.0f && coord <= size) ? 1 : 0;
        const float c  = fminf(fmaxf(coord, 0.0f), size - 1.0f);
        const float lo = floorf(c);
        const float hi = fminf(lo + 1.0f, size - 1.0f);
        const float fr = c - lo;
        if (isx) { s_xlo[g] = (int)lo; s_xhi[g] = (int)hi; s_fx[g] = fr; s_vx[g] = valid; }
        else     { s_ylo[g] = (int)lo; s_yhi[g] = (int)hi; s_fy[g] = fr; s_vy[g] = valid; }
    }
    __syncthreads();

    // float4 gather base: feat4[(y*FW + x)*CHN4] -> warp reads 512B contiguous.
    const float4* feat4 = (const float4*)(g_featT + (size_t)n * PIX * CHN) + cg;

    for (int b = bg; b < NBINS; b += 4) {
        const int ph = b / OUTS;
        const int pw = b - ph * OUTS;
        float4 acc = make_float4(0.f, 0.f, 0.f, 0.f);
#pragma unroll
        for (int sy = 0; sy < SAMPLE; sy++) {
            const int   gy  = ph * SAMPLE + sy;
            const int   ylo = s_ylo[gy];
            const int   yhi = s_yhi[gy];
            const float fy  = s_fy[gy];
            const int   vy  = s_vy[gy];
#pragma unroll
            for (int sx = 0; sx < SAMPLE; sx++) {
                const int gx = pw * SAMPLE + sx;
                if (vy && s_vx[gx]) {
                    const int   xlo = s_xlo[gx];
                    const int   xhi = s_xhi[gx];
                    const float fx  = s_fx[gx];
                    const float4 v00 = feat4[(ylo * FW + xlo) * CHN4];
                    const float4 v01 = feat4[(ylo * FW + xhi) * CHN4];
                    const float4 v10 = feat4[(yhi * FW + xlo) * CHN4];
                    const float4 v11 = feat4[(yhi * FW + xhi) * CHN4];
                    const float w00 = (1.f - fy) * (1.f - fx);
                    const float w01 = (1.f - fy) * fx;
                    const float w10 = fy * (1.f - fx);
                    const float w11 = fy * fx;
                    acc.x += v00.x * w00 + v01.x * w01 + v10.x * w10 + v11.x * w11;
                    acc.y += v00.y * w00 + v01.y * w01 + v10.y * w10 + v11.y * w11;
                    acc.z += v00.z * w00 + v01.z * w01 + v10.z * w10 + v11.z * w11;
                    acc.w += v00.w * w00 + v01.w * w01 + v10.w * w10 + v11.w * w11;
                }
            }
        }
        // out layout per roi: (c, ph, pw) -> c*49 + b. 4-way smem bank conflict
        // on these scalar STS, but staging traffic is tiny (50 KB/CTA).
        const int c0 = cg * 4;
        s_out[(c0 + 0) * NBINS + b] = acc.x * 0.25f;
        s_out[(c0 + 1) * NBINS + b] = acc.y * 0.25f;
        s_out[(c0 + 2) * NBINS + b] = acc.z * 0.25f;
        s_out[(c0 + 3) * NBINS + b] = acc.w * 0.25f;
    }
    __syncthreads();

    // Coalesced store of this roi's (256, 7, 7) block.
    float* o = out + (size_t)k * NBINS * CHN;
    for (int i = tid; i < NBINS * CHN; i += 256) o[i] = s_out[i];
}

extern "C" void kernel_launch(void* const* d_in, const int* in_sizes, int n_in,
                              void* d_out, int out_size) {
    const float* features = (const float*)d_in[0];
    const float* rois     = (const float*)d_in[1];
    float*       out      = (float*)d_out;

    const int K = in_sizes[1] / 5;
    const int smem = NBINS * CHN * (int)sizeof(float);   // 50176 B

    cudaFuncSetAttribute(roialign_kernel,
                         cudaFuncAttributeMaxDynamicSharedMemorySize, smem);

    dim3 tgrid(PIX / 32, CHN / 32, NB);
    transpose_kernel<<<tgrid, dim3(32, 8)>>>(features);

    roialign_kernel<<<K, 256, smem>>>(rois, out);
}